// round 10
// baseline (speedup 1.0000x reference)
#include <cuda_runtime.h>

// Problem constants (fixed by the reference)
constexpr int NB   = 32;   // neighbors per query
constexpr int A    = 4;    // anchors
constexpr int K    = 15;   // kernel points
constexpr int CIN  = 32;
constexpr int COUT = 32;
constexpr int NQ   = 16000;
constexpr int KC   = K * CIN;            // 480
constexpr int QB   = 8;                  // queries per block (stage 1)
constexpr int NT   = NQ * A / 32;        // 2000 stage-2 tiles (32 rows)
constexpr int WF_PADF4 = 121;            // f4 stride per row (odd -> conflict-free LDS.128)
constexpr float INV_EXT = 1.0f / 0.6f;

typedef unsigned long long u64;

// ---- device-global scratch ----
__device__ float g_wf[NQ * A * KC];      // stage-1 output, [na][kc]

// ---- packed f32x2 helpers (bit-identical to scalar fp32 FMA) ----
__device__ __forceinline__ void fma2(u64& acc, u64 a, u64 b) {
    asm("fma.rn.f32x2 %0, %1, %2, %0;" : "+l"(acc) : "l"(a), "l"(b));
}
__device__ __forceinline__ u64 dup2(float x) {
    u64 r; asm("mov.b64 %0, {%1, %1};" : "=l"(r) : "f"(x)); return r;
}
__device__ __forceinline__ float lo32(u64 v) {
    float a, b; asm("mov.b64 {%0, %1}, %2;" : "=f"(a), "=f"(b) : "l"(v)); return a;
}
__device__ __forceinline__ float hi32(u64 v) {
    float a, b; asm("mov.b64 {%0, %1}, %2;" : "=f"(a), "=f"(b) : "l"(v)); return b;
}
__device__ __forceinline__ u64 pack2(float lo, float hi) {
    u64 r; asm("mov.b64 %0, {%1, %2};" : "=l"(r) : "f"(lo), "f"(hi)); return r;
}
__device__ __forceinline__ unsigned s2u(const void* p) {
    unsigned r;
    asm("{ .reg .u64 t; cvta.to.shared.u64 t, %1; cvt.u32.u64 %0, t; }"
        : "=r"(r) : "l"(p));
    return r;
}

// =====================  Kernel 1 (FIRST launch): stages 0+1  =====================
// 256 threads = 8 warps; warp w owns query blockIdx.x*8+w.
// Single b-loop over ALL 4 anchors: lane = (anchor = lane>>3, c4 = (lane&7)*4).
// MLP = 8: eight front-batched LDG.128 per group.
constexpr int S1_W2F   = QB * NB * 68;
constexpr int S1_SMEMB = S1_W2F * 4 + 64 * 16 + QB * 32 * 4;

__global__ __launch_bounds__(256, 2) void stage1_kernel(
    const float* __restrict__ q_pts,
    const float* __restrict__ s_pts,
    const int*   __restrict__ nbr,
    const float* __restrict__ x,
    const float* __restrict__ kp,
    const float* __restrict__ anchors)
{
    extern __shared__ float sm[];
    float*  s_w2   = sm;                           // [8 warps][32 b][68]
    float4* s_kp   = (float4*)(sm + S1_W2F);       // [A*16]
    int*    s_addr = (int*)(sm + S1_W2F + 64 * 4); // [8 warps][32 b]

    const int tid  = threadIdx.x;
    const int w    = tid >> 5;
    const int lane = tid & 31;
    const int q    = blockIdx.x * QB + w;

    if (tid < A * K) {
        int a = tid / K;
        int k = tid - a * K;
        float p0 = kp[k * 3 + 0], p1 = kp[k * 3 + 1], p2 = kp[k * 3 + 2];
        const float* R = anchors + a * 9;
        float r0 = R[0] * p0 + R[1] * p1 + R[2] * p2;
        float r1 = R[3] * p0 + R[4] * p1 + R[5] * p2;
        float r2 = R[6] * p0 + R[7] * p1 + R[8] * p2;
        s_kp[a * 16 + k] = make_float4(r0, r1, r2, r0 * r0 + r1 * r1 + r2 * r2);
    }

    // stage 0: gather + center (lane = neighbor b)
    int m = nbr[q * NB + lane];
    s_addr[w * 32 + lane] = m * 32;     // float4 units
    float dx = s_pts[m * 3 + 0] - q_pts[q * 3 + 0];
    float dy = s_pts[m * 3 + 1] - q_pts[q * 3 + 1];
    float dz = s_pts[m * 3 + 2] - q_pts[q * 3 + 2];
    float n2 = dx * dx + dy * dy + dz * dz;
    __syncthreads();

    // phase A: influence weights for ALL anchors (lane = b)
    float* swq = s_w2 + w * (NB * 68);
    #pragma unroll
    for (int a = 0; a < A; a++) {
        float wk[16];
        #pragma unroll
        for (int k = 0; k < K; k++) {
            float4 g = s_kp[a * 16 + k];
            float cross = dx * g.x + dy * g.y + dz * g.z;
            float sq = fmaxf(fmaf(-2.0f, cross, n2 + g.w), 1e-12f);
            wk[k] = fmaxf(1.0f - sqrtf(sq) * INV_EXT, 0.0f);
        }
        wk[15] = 0.0f;
        float4* dst = (float4*)(swq + lane * 68 + a * 16);
        dst[0] = make_float4(wk[0],  wk[1],  wk[2],  wk[3]);
        dst[1] = make_float4(wk[4],  wk[5],  wk[6],  wk[7]);
        dst[2] = make_float4(wk[8],  wk[9],  wk[10], wk[11]);
        dst[3] = make_float4(wk[12], wk[13], wk[14], wk[15]);
    }
    __syncwarp();

    // phase B: single b-loop, lane's anchor slice; 8 LDGs batched up front.
    u64 acc[4][8];
    #pragma unroll
    for (int c = 0; c < 4; c++)
        #pragma unroll
        for (int j = 0; j < 8; j++) acc[c][j] = 0ULL;

    const float4* xrow   = (const float4*)x;
    const int*    myaddr = s_addr + w * 32;
    const float*  wkbase = swq + (lane >> 3) * 16;

#define S1_PROC(XQ, BB)                                                        \
    {                                                                          \
        const ulonglong2* wp_ = (const ulonglong2*)(wkbase + (BB) * 68);       \
        ulonglong2 k01 = wp_[0], k23 = wp_[1], k45 = wp_[2], k67 = wp_[3];     \
        u64 d0 = dup2((XQ).x), d1 = dup2((XQ).y),                              \
            d2 = dup2((XQ).z), d3 = dup2((XQ).w);                              \
        fma2(acc[0][0], k01.x, d0); fma2(acc[0][1], k01.y, d0);                \
        fma2(acc[0][2], k23.x, d0); fma2(acc[0][3], k23.y, d0);                \
        fma2(acc[0][4], k45.x, d0); fma2(acc[0][5], k45.y, d0);                \
        fma2(acc[0][6], k67.x, d0); fma2(acc[0][7], k67.y, d0);                \
        fma2(acc[1][0], k01.x, d1); fma2(acc[1][1], k01.y, d1);                \
        fma2(acc[1][2], k23.x, d1); fma2(acc[1][3], k23.y, d1);                \
        fma2(acc[1][4], k45.x, d1); fma2(acc[1][5], k45.y, d1);                \
        fma2(acc[1][6], k67.x, d1); fma2(acc[1][7], k67.y, d1);                \
        fma2(acc[2][0], k01.x, d2); fma2(acc[2][1], k01.y, d2);                \
        fma2(acc[2][2], k23.x, d2); fma2(acc[2][3], k23.y, d2);                \
        fma2(acc[2][4], k45.x, d2); fma2(acc[2][5], k45.y, d2);                \
        fma2(acc[2][6], k67.x, d2); fma2(acc[2][7], k67.y, d2);                \
        fma2(acc[3][0], k01.x, d3); fma2(acc[3][1], k01.y, d3);                \
        fma2(acc[3][2], k23.x, d3); fma2(acc[3][3], k23.y, d3);                \
        fma2(acc[3][4], k45.x, d3); fma2(acc[3][5], k45.y, d3);                \
        fma2(acc[3][6], k67.x, d3); fma2(acc[3][7], k67.y, d3);                \
    }

    #pragma unroll 1
    for (int b0 = 0; b0 < NB; b0 += 8) {
        float4 xv[8];
        #pragma unroll
        for (int j = 0; j < 8; j++) xv[j] = __ldg(xrow + myaddr[b0 + j] + lane);
        #pragma unroll
        for (int j = 0; j < 8; j++) S1_PROC(xv[j], b0 + j)
    }
#undef S1_PROC

    // store wf: lane's anchor row, 4 channels, 15 k's
    {
        const int a  = lane >> 3;
        const int c4 = (lane & 7) * 4;
        float* dst = g_wf + ((long)(q * A + a)) * KC + c4;
        #pragma unroll
        for (int j = 0; j < 8; j++) {
            *(float4*)(dst + (2 * j) * CIN) =
                make_float4(lo32(acc[0][j]), lo32(acc[1][j]),
                            lo32(acc[2][j]), lo32(acc[3][j]));
            if (j < 7) {
                *(float4*)(dst + (2 * j + 1) * CIN) =
                    make_float4(hi32(acc[0][j]), hi32(acc[1][j]),
                                hi32(acc[2][j]), hi32(acc[3][j]));
            }
        }
    }
}

// =====================  Kernel 2: persistent stage-2 GEMM  =====================
// [64000 x 480] @ [480 x 32]. 152 blocks x 512 threads, 1/SM.
// Single-tile passes, DOUBLE-BUFFERED via cp.async (load fully hidden).
// 16 warps = 2 col-groups (16 cols) x 8 kc-eighths (60 kc). Per 4-kc iter:
// 1 per-lane f LDS.128 + 16 broadcast weight LDS.128 for 32 FFMA2.
constexpr int S2_WU     = (KC / 2) * COUT;        // 7680 packed u64 weights
constexpr int S2_TILEF4 = 32 * WF_PADF4;          // 3872 f4 per tile buffer
constexpr int S2_SMEMB  = S2_WU * 8 + 2 * S2_TILEF4 * 16 + 8 * 32 * 8 * 16; // 218112

__device__ __forceinline__ void load_tile_async(float4* dst, const float4* src, int tid) {
    #pragma unroll
    for (int j = 0; j < 8; j++) {
        int i = tid + j * 512;
        if (i < 3840) {                       // 32 rows x 120 f4
            int row = i / 120;
            int c4  = i - row * 120;
            asm volatile("cp.async.cg.shared.global [%0], [%1], 16;"
                         :: "r"(s2u(dst + row * WF_PADF4 + c4)),
                            "l"(src + i) : "memory");
        }
    }
}

__global__ __launch_bounds__(512, 1) void stage2_kernel(
    const float* __restrict__ weights, float* __restrict__ out)
{
    extern __shared__ float sm2[];
    u64*    sw   = (u64*)sm2;                              // [7680]
    float4* st   = (float4*)(sm2 + S2_WU * 2);             // [2][3872]
    float4* part = st + 2 * S2_TILEF4;                     // [8 e][32 row][8 f4]

    const int tid  = threadIdx.x;
    const int w    = tid >> 5;
    const int lane = tid & 31;
    const int cg   = w & 1;        // col-group: cols 16cg..16cg+15
    const int e    = w >> 1;       // kc eighth: quads [15e, 15e+15)
    const int dc   = cg * 16;

    // pack weights into smem once: sw[p*32+d] = (W[2p][d], W[2p+1][d])
    for (int i = tid; i < S2_WU; i += 512) {
        int p = i >> 5;
        int d = i & 31;
        sw[i] = pack2(__ldg(weights + (2 * p) * COUT + d),
                      __ldg(weights + (2 * p + 1) * COUT + d));
    }

    // prime buffer 0 with this block's first tile
    load_tile_async(st, (const float4*)(g_wf + (long)blockIdx.x * 32 * KC), tid);
    asm volatile("cp.async.commit_group;" ::: "memory");

    int cur = 0;
    for (int t = blockIdx.x; t < NT; t += gridDim.x) {
        // prefetch next tile into the other buffer (possibly empty group)
        int tn = t + gridDim.x;
        if (tn < NT)
            load_tile_async(st + (cur ^ 1) * S2_TILEF4,
                            (const float4*)(g_wf + (long)tn * 32 * KC), tid);
        asm volatile("cp.async.commit_group;" ::: "memory");
        asm volatile("cp.async.wait_group 1;" ::: "memory");  // tile `cur` ready
        __syncthreads();

        const ulonglong2* fw = (const ulonglong2*)(st + cur * S2_TILEF4 +
                                                   lane * WF_PADF4 + e * 15);
        const u64* wq = sw + (e * 30) * COUT;   // pair rows for this eighth

        u64 acc[16];
        #pragma unroll
        for (int c = 0; c < 16; c++) acc[c] = 0ULL;

        #pragma unroll 3
        for (int i = 0; i < 15; i++) {
            ulonglong2 f = fw[i];               // (wf[4k],wf[4k+1]) , (wf[4k+2],wf[4k+3])
            const u64* wep = wq + (2 * i) * COUT + dc;   // even pair, 16 cols
            #pragma unroll
            for (int c = 0; c < 8; c++) {
                ulonglong2 we = *(const ulonglong2*)(wep + 2 * c);
                fma2(acc[2 * c],     f.x, we.x);
                fma2(acc[2 * c + 1], f.x, we.y);
            }
            const u64* wop = wep + COUT;                 // odd pair
            #pragma unroll
            for (int c = 0; c < 8; c++) {
                ulonglong2 wo = *(const ulonglong2*)(wop + 2 * c);
                fma2(acc[2 * c],     f.y, wo.x);
                fma2(acc[2 * c + 1], f.y, wo.y);
            }
        }

        // partials: part[e][lane][cg*4 + j]
        float4* pp = part + (e * 32 + lane) * 8 + cg * 4;
        #pragma unroll
        for (int j = 0; j < 4; j++) {
            pp[j] = make_float4(
                lo32(acc[4 * j + 0]) + hi32(acc[4 * j + 0]),
                lo32(acc[4 * j + 1]) + hi32(acc[4 * j + 1]),
                lo32(acc[4 * j + 2]) + hi32(acc[4 * j + 2]),
                lo32(acc[4 * j + 3]) + hi32(acc[4 * j + 3]));
        }
        __syncthreads();

        // reduce 8 eighths + store (256 threads: row = tid>>3, j = tid&7)
        if (tid < 256) {
            int row = tid >> 3;
            int j   = tid & 7;
            float4 v0 = part[(0 * 32 + row) * 8 + j];
            float4 v1 = part[(1 * 32 + row) * 8 + j];
            float4 v2 = part[(2 * 32 + row) * 8 + j];
            float4 v3 = part[(3 * 32 + row) * 8 + j];
            float4 v4 = part[(4 * 32 + row) * 8 + j];
            float4 v5 = part[(5 * 32 + row) * 8 + j];
            float4 v6 = part[(6 * 32 + row) * 8 + j];
            float4 v7 = part[(7 * 32 + row) * 8 + j];
            float4 v = make_float4(
                ((v0.x + v1.x) + (v2.x + v3.x)) + ((v4.x + v5.x) + (v6.x + v7.x)),
                ((v0.y + v1.y) + (v2.y + v3.y)) + ((v4.y + v5.y) + (v6.y + v7.y)),
                ((v0.z + v1.z) + (v2.z + v3.z)) + ((v4.z + v5.z) + (v6.z + v7.z)),
                ((v0.w + v1.w) + (v2.w + v3.w)) + ((v4.w + v5.w) + (v6.w + v7.w)));
            *(float4*)(out + ((long)t * 32 + row) * COUT + j * 4) = v;
        }
        cur ^= 1;
        // next iter's cp.async writes the buffer this pass computed from; all
        // compute reads completed before the partials __syncthreads above.
    }
}

extern "C" void kernel_launch(void* const* d_in, const int* in_sizes, int n_in,
                              void* d_out, int out_size) {
    const float* q_pts   = (const float*)d_in[0];
    const float* s_pts   = (const float*)d_in[1];
    const int*   nbr     = (const int*)  d_in[2];
    const float* x       = (const float*)d_in[3];
    const float* kp      = (const float*)d_in[4];
    const float* anchors = (const float*)d_in[5];
    const float* weights = (const float*)d_in[6];
    float* out = (float*)d_out;

    const int Nq = in_sizes[2] / NB;   // 16000

    static bool attr_set = false;
    if (!attr_set) {
        cudaFuncSetAttribute(stage1_kernel,
                             cudaFuncAttributeMaxDynamicSharedMemorySize, S1_SMEMB);
        cudaFuncSetAttribute(stage2_kernel,
                             cudaFuncAttributeMaxDynamicSharedMemorySize, S2_SMEMB);
        attr_set = true;
    }

    stage1_kernel<<<Nq / QB, 256, S1_SMEMB>>>(q_pts, s_pts, nbr, x, kp, anchors);
    stage2_kernel<<<152, 512, S2_SMEMB>>>(weights, out);
}